// round 10
// baseline (speedup 1.0000x reference)
#include <cuda_runtime.h>
#include <math.h>

#define BATCH 4
#define SEQ 8192
#define DIMN 1024
#define RCH 32                      /* rows per chunk (= per block) */
#define CPB (SEQ / RCH)             /* 256 chunks per batch */
#define NCHT (BATCH * CPB)          /* 1024 chunks total */
#define NSEG 16
#define SEGLEN (CPB / NSEG)         /* 16 */
#define NFLAG (BATCH * NSEG * 4)    /* 256: one per (b, seg, ch-quarter) */
#define LN_EPS_F 1e-5f
#define FULLMASK 0xffffffffu
#define SENT_BITS 0x7fbfffffu       /* NaN sentinel for unpublished stats */

// Scratch
__device__ float  g_S[NCHT * DIMN];          // chunk-final local z states (4 MB)
__device__ float  g_P[NCHT * DIMN];          // chunk entry carries (4 MB)
__device__ float  g_A[BATCH * NSEG * DIMN];  // segment aggregates (256 KB)
__device__ float2 g_stats[BATCH * SEQ];      // per-row (inv, nm) (256 KB)
__device__ unsigned g_cflag[NFLAG];          // segment-aggregate publish flags

__device__ __forceinline__ float sigm_om(const float* __restrict__ alphas, int head) {
    float al = __ldg(alphas + head);
    return 1.0f - 1.0f / (1.0f + expf(-al));      // om = 1 - sigmoid(alpha)
}
__device__ __forceinline__ float pow32(float om) {
    float t = om * om;  t = t * t;  t = t * t;  t = t * t;  t = t * t;   // om^32
    return t;
}

// ---------------- Pass 1: warp-specialized LN stats + local z-scan ----------
// 384 threads: warps 0-7 = scan (thread owns channels tid*4..+3, one head,
// no shuffles/barriers), warps 8-11 = stats (row r handled by warp 8 + r%4;
// re-reads the row from global -- L1/miss-in-flight hit -- reduces privately,
// publishes (inv,nm) as one volatile 8B smem store).
__global__ __launch_bounds__(384, 3) void mhesa_pass1(
    const float* __restrict__ x, const float* __restrict__ gamma,
    const float* __restrict__ beta, const float* __restrict__ alphas)
{
    __shared__ float2 s_st[RCH];

    const int tid = threadIdx.x;
    const int chunk = blockIdx.x;               // 0..NCHT-1
    const int bat = chunk >> 8;                 // / CPB
    const int c = chunk & (CPB - 1);
    const size_t rowbase = ((size_t)bat * SEQ + (size_t)c * RCH) * DIMN;
    const int row0 = bat * SEQ + c * RCH;

    // reset carry flags for this run (kernel ordering makes this race-free)
    if (tid == 0 && blockIdx.x < NFLAG) g_cflag[blockIdx.x] = 0u;

    if (tid < RCH) s_st[tid] = make_float2(__uint_as_float(SENT_BITS), 0.f);
    __syncthreads();

    if (tid < 256) {
        // ================= scan role =================
        const int ch4 = tid * 4;
        const float om = sigm_om(alphas, ch4 >> 7);
        const float4 g  = *(const float4*)(gamma + ch4);
        const float4 bb = *(const float4*)(beta + ch4);
        const float* xp = x + rowbase + ch4;

        float4 buf[4];
#pragma unroll
        for (int k = 0; k < 4; k++)
            buf[k] = __ldg((const float4*)(xp + (size_t)k * DIMN));

        float4 z = make_float4(0.f, 0.f, 0.f, 0.f);

        for (int rb = 0; rb < RCH; rb += 4) {
#pragma unroll
            for (int k = 0; k < 4; k++) {
                const int r = rb + k;
                const float4 v = buf[k];
                if (r + 4 < RCH)
                    buf[k] = __ldg((const float4*)(xp + (size_t)(r + 4) * DIMN));
                // wait for stats of row r (usually already published)
                float inv, nm;
                {
                    const unsigned addr =
                        (unsigned)__cvta_generic_to_shared(&s_st[r]);
                    asm volatile("ld.volatile.shared.v2.f32 {%0,%1}, [%2];"
                                 : "=f"(inv), "=f"(nm) : "r"(addr));
                    while (__float_as_uint(inv) == SENT_BITS) {
                        __nanosleep(32);
                        asm volatile("ld.volatile.shared.v2.f32 {%0,%1}, [%2];"
                                     : "=f"(inv), "=f"(nm) : "r"(addr));
                    }
                }
                float4 u;
                u.x = fmaf(fmaf(v.x, inv, nm), g.x, bb.x);
                u.y = fmaf(fmaf(v.y, inv, nm), g.y, bb.y);
                u.z = fmaf(fmaf(v.z, inv, nm), g.z, bb.z);
                u.w = fmaf(fmaf(v.w, inv, nm), g.w, bb.w);
                z.x = fmaf(om, z.x, u.x);
                z.y = fmaf(om, z.y, u.y);
                z.z = fmaf(om, z.z, u.z);
                z.w = fmaf(om, z.w, u.w);
            }
        }
        *(float4*)(g_S + (size_t)chunk * DIMN + tid * 4) = z;
    } else {
        // ================= stats role =================
        const int sw = (tid >> 5) - 8;          // 0..3
        const int lane = tid & 31;
        for (int r = sw; r < RCH; r += 4) {
            const float* xp = x + rowbase + (size_t)r * DIMN + lane * 4;
            float4 v[8];
#pragma unroll
            for (int j = 0; j < 8; j++)
                v[j] = __ldg((const float4*)(xp + j * 128));
            float sum = 0.f, sq = 0.f;
#pragma unroll
            for (int j = 0; j < 8; j++) {
                sum += (v[j].x + v[j].y) + (v[j].z + v[j].w);
                sq = fmaf(v[j].x, v[j].x, sq);
                sq = fmaf(v[j].y, v[j].y, sq);
                sq = fmaf(v[j].z, v[j].z, sq);
                sq = fmaf(v[j].w, v[j].w, sq);
            }
#pragma unroll
            for (int off = 16; off; off >>= 1) {
                sum += __shfl_xor_sync(FULLMASK, sum, off);
                sq  += __shfl_xor_sync(FULLMASK, sq,  off);
            }
            if (lane == 0) {
                const float mean = sum * (1.0f / (float)DIMN);
                const float var  = fmaf(sq, 1.0f / (float)DIMN, -mean * mean);
                const float inv  = rsqrtf(var + LN_EPS_F);
                const float nm   = -mean * inv;
                g_stats[row0 + r] = make_float2(inv, nm);
                const unsigned addr =
                    (unsigned)__cvta_generic_to_shared(&s_st[r]);
                asm volatile("st.volatile.shared.v2.f32 [%0], {%1,%2};"
                             :: "r"(addr), "f"(inv), "f"(nm));
            }
        }
    }
}

// ---------------- Merged carry: segment aggregates + lookback + P ----------
// Block = (b, seg, ch-quarter); thread owns one channel. Computes the segment
// aggregate A (S values held in registers), publishes it, folds predecessor
// aggregates (all 256 blocks co-resident -> bounded spin), writes chunk entry
// carries for its segment.
__global__ __launch_bounds__(256, 4) void mhesa_carry(const float* __restrict__ alphas)
{
    const int q = blockIdx.x & 3;
    const int seg = (blockIdx.x >> 2) & (NSEG - 1);
    const int b = blockIdx.x >> 6;
    const int ch = q * 256 + threadIdx.x;

    const float omC = pow32(sigm_om(alphas, ch >> 7));
    float omSeg = omC;                                   // omC^SEGLEN = om^512
    omSeg *= omSeg; omSeg *= omSeg; omSeg *= omSeg; omSeg *= omSeg;

    const size_t base = ((size_t)b * CPB + (size_t)seg * SEGLEN) * DIMN + ch;
    float s[SEGLEN];
#pragma unroll
    for (int j = 0; j < SEGLEN; j++) s[j] = g_S[base + (size_t)j * DIMN];
    float A = 0.f;
#pragma unroll
    for (int j = 0; j < SEGLEN; j++) A = fmaf(omC, A, s[j]);

    // publish aggregate
    {
        float* ap = g_A + ((size_t)b * NSEG + seg) * DIMN + ch;
        asm volatile("st.global.cg.f32 [%0], %1;" :: "l"(ap), "f"(A) : "memory");
    }
    __threadfence();
    __syncthreads();
    if (threadIdx.x == 0) atomicExch(&g_cflag[blockIdx.x], 1u);

    // lookback: fold earlier segments' aggregates (ascending order)
    float p = 0.f;
    for (int s2 = 0; s2 < seg; s2++) {
        const int fidx = ((b * NSEG + s2) << 2) + q;
        if (threadIdx.x == 0) {
            unsigned f;
            do {
                asm volatile("ld.global.cg.u32 %0, [%1];"
                             : "=r"(f) : "l"(&g_cflag[fidx]) : "memory");
            } while (f == 0u);
        }
        __syncthreads();
        __threadfence();
        float Av;
        const float* ap = g_A + ((size_t)b * NSEG + s2) * DIMN + ch;
        asm volatile("ld.global.cg.f32 %0, [%1];" : "=f"(Av) : "l"(ap));
        p = fmaf(omSeg, p, Av);
    }

    // write chunk entry carries for this segment (S already in registers)
#pragma unroll
    for (int j = 0; j < SEGLEN; j++) {
        g_P[base + (size_t)j * DIMN] = p;
        p = fmaf(omC, p, s[j]);
    }
}

// ---------------- Pass 2: pure stream, no reductions ----------------
__global__ __launch_bounds__(256, 4) void mhesa_pass2(
    const float* __restrict__ x, const float* __restrict__ gamma,
    const float* __restrict__ beta, const float* __restrict__ alphas,
    const float* __restrict__ paramD, float* __restrict__ out)
{
    const int tid = threadIdx.x;
    const int ch4 = tid * 4;
    const int chunk = NCHT - 1 - blockIdx.x;    // reverse: reuse pass1's L2 tail
    const int bat = chunk >> 8;
    const int c = chunk & (CPB - 1);

    const float om = sigm_om(alphas, ch4 >> 7);
    const float a = 1.0f - om;
    const float4 g  = *(const float4*)(gamma + ch4);
    const float4 bb = *(const float4*)(beta + ch4);
    const float4 d  = *(const float4*)(paramD + ch4);

    const size_t base = ((size_t)bat * SEQ + (size_t)c * RCH) * DIMN + ch4;
    const int row0 = bat * SEQ + c * RCH;

    float4 z = *(const float4*)(g_P + (size_t)chunk * DIMN + ch4);

    float4 buf[4];
#pragma unroll
    for (int k = 0; k < 4; k++)
        buf[k] = __ldcs((const float4*)(x + base + (size_t)k * DIMN));

    for (int rb = 0; rb < RCH; rb += 4) {
#pragma unroll
        for (int k = 0; k < 4; k++) {
            const int r = rb + k;
            const float4 v = buf[k];
            if (r + 4 < RCH)
                buf[k] = __ldcs((const float4*)(x + base + (size_t)(r + 4) * DIMN));
            const float2 st = __ldg(&g_stats[row0 + r]);   // (inv, nm), warp-broadcast
            const float inv = st.x, nm = st.y;
            float4 u;
            u.x = fmaf(fmaf(v.x, inv, nm), g.x, bb.x);
            u.y = fmaf(fmaf(v.y, inv, nm), g.y, bb.y);
            u.z = fmaf(fmaf(v.z, inv, nm), g.z, bb.z);
            u.w = fmaf(fmaf(v.w, inv, nm), g.w, bb.w);
            z.x = fmaf(om, z.x, u.x);
            z.y = fmaf(om, z.y, u.y);
            z.z = fmaf(om, z.z, u.z);
            z.w = fmaf(om, z.w, u.w);
            float4 o;
            o.x = fmaf(u.x, d.x, a * z.x);
            o.y = fmaf(u.y, d.y, a * z.y);
            o.z = fmaf(u.z, d.z, a * z.z);
            o.w = fmaf(u.w, d.w, a * z.w);
            __stcs((float4*)(out + base + (size_t)r * DIMN), o);
        }
    }
}

extern "C" void kernel_launch(void* const* d_in, const int* in_sizes, int n_in,
                              void* d_out, int out_size)
{
    const float* x      = (const float*)d_in[0];
    const float* gamma  = (const float*)d_in[1];
    const float* beta   = (const float*)d_in[2];
    const float* alphas = (const float*)d_in[3];
    const float* paramD = (const float*)d_in[4];
    float* out = (float*)d_out;

    mhesa_pass1<<<NCHT, 384>>>(x, gamma, beta, alphas);
    mhesa_carry<<<NFLAG, 256>>>(alphas);
    mhesa_pass2<<<NCHT, 256>>>(x, gamma, beta, alphas, paramD, out);
}

// round 11
// speedup vs baseline: 1.0798x; 1.0798x over previous
#include <cuda_runtime.h>
#include <math.h>
#include <stdint.h>

#define BATCH 4
#define SEQ 8192
#define DIMN 1024
#define RCH 32                      /* rows per chunk (= per block) */
#define CPB (SEQ / RCH)             /* 256 chunks per batch */
#define NCHT (BATCH * CPB)          /* 1024 chunks total */
#define NSEG 16
#define SEGLEN (CPB / NSEG)         /* 16 */
#define LN_EPS_F 1e-5f
#define FULLMASK 0xffffffffu
#define SENT_BITS 0x7fbfffffu       /* NaN sentinel for unpublished stats */

/* pass1 TMA pipeline */
#define TILEROWS 8
#define TILE_BYTES (TILEROWS * DIMN * 4)   /* 32768 */
#define NTILES (RCH / TILEROWS)            /* 4 */
#define STAGES 3
#define SM_MBAR 0                          /* 3 mbarriers, 8 B each */
#define SM_ST 64                           /* 32 float2 stat slots */
#define SM_TILES 1024
#define SMEM_P1 (SM_TILES + STAGES * TILE_BYTES)   /* 99328 */

// Scratch
__device__ float  g_S[NCHT * DIMN];          // chunk-final local z states (4 MB)
__device__ float  g_P[NCHT * DIMN];          // chunk entry carries (4 MB)
__device__ float  g_A[BATCH * NSEG * DIMN];  // segment aggregates (256 KB)
__device__ float2 g_stats[BATCH * SEQ];      // per-row (inv, nm) (256 KB)

__device__ __forceinline__ float sigm_om(const float* __restrict__ alphas, int head) {
    float al = __ldg(alphas + head);
    return 1.0f - 1.0f / (1.0f + expf(-al));      // om = 1 - sigmoid(alpha)
}
__device__ __forceinline__ float pow32(float om) {
    float t = om * om;  t = t * t;  t = t * t;  t = t * t;  t = t * t;   // om^32
    return t;
}

__device__ __forceinline__ void mbar_init(uint32_t mbar, uint32_t count) {
    asm volatile("mbarrier.init.shared.b64 [%0], %1;" :: "r"(mbar), "r"(count) : "memory");
}
__device__ __forceinline__ void mbar_expect_tx(uint32_t mbar, uint32_t bytes) {
    asm volatile("mbarrier.arrive.expect_tx.shared.b64 _, [%0], %1;"
                 :: "r"(mbar), "r"(bytes) : "memory");
}
__device__ __forceinline__ void bulk_ld(uint32_t dst, const void* src, uint32_t bytes,
                                        uint32_t mbar) {
    asm volatile("cp.async.bulk.shared::cluster.global.mbarrier::complete_tx::bytes "
                 "[%0], [%1], %2, [%3];"
                 :: "r"(dst), "l"(src), "r"(bytes), "r"(mbar) : "memory");
}
__device__ __forceinline__ void mbar_wait(uint32_t mbar, uint32_t parity) {
    uint32_t done;
    asm volatile("{\n\t.reg .pred p;\n\t"
                 "mbarrier.try_wait.parity.acquire.cta.shared::cta.b64 p, [%1], %2;\n\t"
                 "selp.b32 %0, 1, 0, p;\n\t}"
                 : "=r"(done) : "r"(mbar), "r"(parity) : "memory");
    if (!done) {
        asm volatile("{\n\t.reg .pred P1;\n\t"
                     "W%=:\n\t"
                     "mbarrier.try_wait.parity.acquire.cta.shared::cta.b64 P1, [%0], %1, 0x989680;\n\t"
                     "@P1 bra.uni D%=;\n\t"
                     "bra.uni W%=;\n\t"
                     "D%=:\n\t}"
                     :: "r"(mbar), "r"(parity) : "memory");
    }
}

// ---------------- Pass 1: TMA-fed, warp-specialized LN stats + z-scan -------
// 384 threads. TMA bulk loads 32KB tiles (8 rows) into a 3-stage smem ring.
// Warps 0-7 (256 thr): scan role, thread owns channels tid*4..+3 (one head).
// Warps 8-11: stats role, warp sw reduces tile rows {2sw, 2sw+1} from smem,
// publishes (inv,nm) via one volatile 8B smem store (per-chunk-unique slots).
__global__ __launch_bounds__(384, 2) void mhesa_pass1(
    const float* __restrict__ x, const float* __restrict__ gamma,
    const float* __restrict__ beta, const float* __restrict__ alphas)
{
    extern __shared__ __align__(16) char smem[];
    const uint32_t smem_base = (uint32_t)__cvta_generic_to_shared(smem);

    const int tid = threadIdx.x;
    const int chunk = blockIdx.x;               // 0..NCHT-1
    const int bat = chunk >> 8;                 // / CPB
    const int c = chunk & (CPB - 1);
    const size_t rowbase = ((size_t)bat * SEQ + (size_t)c * RCH) * DIMN;
    const int row0 = bat * SEQ + c * RCH;
    const float* xchunk = x + rowbase;          // 128KB contiguous

    if (tid == 0) {
#pragma unroll
        for (int s = 0; s < STAGES; s++) mbar_init(smem_base + SM_MBAR + 8 * s, 1);
    }
    if (tid < RCH)
        *(float2*)(smem + SM_ST + tid * 8) = make_float2(__uint_as_float(SENT_BITS), 0.f);
    asm volatile("fence.proxy.async.shared::cta;" ::: "memory");
    __syncthreads();

    if (tid == 0) {
#pragma unroll
        for (int t = 0; t < STAGES; t++) {
            const uint32_t mb = smem_base + SM_MBAR + 8 * t;
            mbar_expect_tx(mb, TILE_BYTES);
            bulk_ld(smem_base + SM_TILES + t * TILE_BYTES,
                    xchunk + (size_t)t * TILEROWS * DIMN, TILE_BYTES, mb);
        }
    }

    float4 z = make_float4(0.f, 0.f, 0.f, 0.f);
    float om = 0.f;
    float4 g, bb;
    if (tid < 256) {
        const int ch4 = tid * 4;
        om = sigm_om(alphas, ch4 >> 7);
        g  = *(const float4*)(gamma + ch4);
        bb = *(const float4*)(beta + ch4);
    }
    const int sw = (tid >> 5) - 8;              // stats warp idx (valid if >=0)
    const int lane = tid & 31;

    for (int t = 0; t < NTILES; t++) {
        const int stage = t % STAGES;
        const uint32_t mb = smem_base + SM_MBAR + 8 * stage;
        mbar_wait(mb, (uint32_t)(t / STAGES));
        const char* tile = smem + SM_TILES + stage * TILE_BYTES;

        if (tid < 256) {
            // ---- scan role: slurp 8 rows from smem, then consume in order ----
            const int ch4 = tid * 4;
            float4 xr[TILEROWS];
#pragma unroll
            for (int k = 0; k < TILEROWS; k++)
                xr[k] = *(const float4*)(tile + (size_t)k * DIMN * 4 + ch4 * 4);
#pragma unroll
            for (int k = 0; k < TILEROWS; k++) {
                const int r = t * TILEROWS + k;
                float inv, nm;
                const uint32_t addr = smem_base + SM_ST + r * 8;
                asm volatile("ld.volatile.shared.v2.f32 {%0,%1}, [%2];"
                             : "=f"(inv), "=f"(nm) : "r"(addr));
                while (__float_as_uint(inv) == SENT_BITS) {
                    __nanosleep(20);
                    asm volatile("ld.volatile.shared.v2.f32 {%0,%1}, [%2];"
                                 : "=f"(inv), "=f"(nm) : "r"(addr));
                }
                const float4 v = xr[k];
                float4 u;
                u.x = fmaf(fmaf(v.x, inv, nm), g.x, bb.x);
                u.y = fmaf(fmaf(v.y, inv, nm), g.y, bb.y);
                u.z = fmaf(fmaf(v.z, inv, nm), g.z, bb.z);
                u.w = fmaf(fmaf(v.w, inv, nm), g.w, bb.w);
                z.x = fmaf(om, z.x, u.x);
                z.y = fmaf(om, z.y, u.y);
                z.z = fmaf(om, z.z, u.z);
                z.w = fmaf(om, z.w, u.w);
            }
        } else {
            // ---- stats role: rows 2sw, 2sw+1 of this tile ----
#pragma unroll
            for (int rr = 0; rr < 2; rr++) {
                const int rl = sw * 2 + rr;
                const int r = t * TILEROWS + rl;
                const char* rowp = tile + (size_t)rl * DIMN * 4 + lane * 16;
                float4 v[8];
#pragma unroll
                for (int j = 0; j < 8; j++)
                    v[j] = *(const float4*)(rowp + j * 512);
                float sum = 0.f, sq = 0.f;
#pragma unroll
                for (int j = 0; j < 8; j++) {
                    sum += (v[j].x + v[j].y) + (v[j].z + v[j].w);
                    sq = fmaf(v[j].x, v[j].x, sq);
                    sq = fmaf(v[j].y, v[j].y, sq);
                    sq = fmaf(v[j].z, v[j].z, sq);
                    sq = fmaf(v[j].w, v[j].w, sq);
                }
#pragma unroll
                for (int off = 16; off; off >>= 1) {
                    sum += __shfl_xor_sync(FULLMASK, sum, off);
                    sq  += __shfl_xor_sync(FULLMASK, sq,  off);
                }
                if (lane == 0) {
                    const float mean = sum * (1.0f / (float)DIMN);
                    const float var  = fmaf(sq, 1.0f / (float)DIMN, -mean * mean);
                    const float inv  = rsqrtf(var + LN_EPS_F);
                    const float nm   = -mean * inv;
                    g_stats[row0 + r] = make_float2(inv, nm);
                    const uint32_t addr = smem_base + SM_ST + r * 8;
                    asm volatile("st.volatile.shared.v2.f32 [%0], {%1,%2};"
                                 :: "r"(addr), "f"(inv), "f"(nm));
                }
            }
        }
        __syncthreads();                         // stage fully consumed
        if (tid == 0 && t + STAGES < NTILES) {
            const int nt = t + STAGES;
            const uint32_t mb2 = smem_base + SM_MBAR + 8 * (nt % STAGES);
            mbar_expect_tx(mb2, TILE_BYTES);
            bulk_ld(smem_base + SM_TILES + (nt % STAGES) * TILE_BYTES,
                    xchunk + (size_t)nt * TILEROWS * DIMN, TILE_BYTES, mb2);
        }
    }

    if (tid < 256)
        *(float4*)(g_S + (size_t)chunk * DIMN + tid * 4) = z;
}

// ---------------- Carry phase A: segment aggregates ----------------
__global__ void mhesa_carryA(const float* __restrict__ alphas)
{
    const int t = blockIdx.x * 256 + threadIdx.x;       // 0..65535
    const int ch = t & (DIMN - 1);
    const int rest = t >> 10;                            // b*NSEG + seg
    const float omC = pow32(sigm_om(alphas, ch >> 7));
    const size_t base = (size_t)rest * SEGLEN * DIMN + ch;
    float s[SEGLEN];
#pragma unroll
    for (int j = 0; j < SEGLEN; j++) s[j] = g_S[base + (size_t)j * DIMN];
    float A = 0.f;
#pragma unroll
    for (int j = 0; j < SEGLEN; j++) A = fmaf(omC, A, s[j]);
    g_A[(size_t)rest * DIMN + ch] = A;
}

// ---------------- Carry phase C: chunk entry carries ----------------
__global__ void mhesa_carryC(const float* __restrict__ alphas)
{
    const int t = blockIdx.x * 256 + threadIdx.x;
    const int ch = t & (DIMN - 1);
    const int rest = t >> 10;
    const int seg = rest & (NSEG - 1);
    const int b = rest >> 4;
    const float omC = pow32(sigm_om(alphas, ch >> 7));
    float omSeg = omC;                                   // omC^SEGLEN = om^512
    omSeg = omSeg * omSeg; omSeg = omSeg * omSeg;
    omSeg = omSeg * omSeg; omSeg = omSeg * omSeg;

    float p = 0.f;
    const size_t abase = (size_t)b * NSEG * DIMN + ch;
    for (int s2 = 0; s2 < seg; s2++)
        p = fmaf(omSeg, p, g_A[abase + (size_t)s2 * DIMN]);

    const size_t base = (size_t)rest * SEGLEN * DIMN + ch;
    float s[SEGLEN];
#pragma unroll
    for (int j = 0; j < SEGLEN; j++) s[j] = g_S[base + (size_t)j * DIMN];
#pragma unroll
    for (int j = 0; j < SEGLEN; j++) {
        g_P[base + (size_t)j * DIMN] = p;
        p = fmaf(omC, p, s[j]);
    }
}

// ---------------- Pass 2: pure stream, no reductions ----------------
__global__ __launch_bounds__(256, 4) void mhesa_pass2(
    const float* __restrict__ x, const float* __restrict__ gamma,
    const float* __restrict__ beta, const float* __restrict__ alphas,
    const float* __restrict__ paramD, float* __restrict__ out)
{
    const int tid = threadIdx.x;
    const int ch4 = tid * 4;
    const int chunk = NCHT - 1 - blockIdx.x;    // reverse: reuse pass1's L2 tail
    const int bat = chunk >> 8;
    const int c = chunk & (CPB - 1);

    const float om = sigm_om(alphas, ch4 >> 7);
    const float a = 1.0f - om;
    const float4 g  = *(const float4*)(gamma + ch4);
    const float4 bb = *(const float4*)(beta + ch4);
    const float4 d  = *(const float4*)(paramD + ch4);

    const size_t base = ((size_t)bat * SEQ + (size_t)c * RCH) * DIMN + ch4;
    const int row0 = bat * SEQ + c * RCH;

    float4 z = *(const float4*)(g_P + (size_t)chunk * DIMN + ch4);

    float4 buf[4];
#pragma unroll
    for (int k = 0; k < 4; k++)
        buf[k] = __ldg((const float4*)(x + base + (size_t)k * DIMN));

    for (int rb = 0; rb < RCH; rb += 4) {
#pragma unroll
        for (int k = 0; k < 4; k++) {
            const int r = rb + k;
            const float4 v = buf[k];
            if (r + 4 < RCH)
                buf[k] = __ldg((const float4*)(x + base + (size_t)(r + 4) * DIMN));
            const float2 st = __ldg(&g_stats[row0 + r]);   // (inv, nm), warp-broadcast
            const float inv = st.x, nm = st.y;
            float4 u;
            u.x = fmaf(fmaf(v.x, inv, nm), g.x, bb.x);
            u.y = fmaf(fmaf(v.y, inv, nm), g.y, bb.y);
            u.z = fmaf(fmaf(v.z, inv, nm), g.z, bb.z);
            u.w = fmaf(fmaf(v.w, inv, nm), g.w, bb.w);
            z.x = fmaf(om, z.x, u.x);
            z.y = fmaf(om, z.y, u.y);
            z.z = fmaf(om, z.z, u.z);
            z.w = fmaf(om, z.w, u.w);
            float4 o;
            o.x = fmaf(u.x, d.x, a * z.x);
            o.y = fmaf(u.y, d.y, a * z.y);
            o.z = fmaf(u.z, d.z, a * z.z);
            o.w = fmaf(u.w, d.w, a * z.w);
            __stcs((float4*)(out + base + (size_t)r * DIMN), o);
        }
    }
}

extern "C" void kernel_launch(void* const* d_in, const int* in_sizes, int n_in,
                              void* d_out, int out_size)
{
    const float* x      = (const float*)d_in[0];
    const float* gamma  = (const float*)d_in[1];
    const float* beta   = (const float*)d_in[2];
    const float* alphas = (const float*)d_in[3];
    const float* paramD = (const float*)d_in[4];
    float* out = (float*)d_out;

    static int attr_done = 0;
    if (!attr_done) {
        cudaFuncSetAttribute(mhesa_pass1,
                             cudaFuncAttributeMaxDynamicSharedMemorySize, SMEM_P1);
        attr_done = 1;
    }

    mhesa_pass1<<<NCHT, 384, SMEM_P1>>>(x, gamma, beta, alphas);
    mhesa_carryA<<<(BATCH * NSEG * DIMN) / 256, 256>>>(alphas);
    mhesa_carryC<<<(BATCH * NSEG * DIMN) / 256, 256>>>(alphas);
    mhesa_pass2<<<NCHT, 256>>>(x, gamma, beta, alphas, paramD, out);
}

// round 12
// speedup vs baseline: 1.1449x; 1.0603x over previous
#include <cuda_runtime.h>
#include <math.h>

#define BATCH 4
#define SEQ 8192
#define DIMN 1024
#define RCH 32                      /* rows per chunk (= per block) */
#define CPB (SEQ / RCH)             /* 256 chunks per batch */
#define NCHT (BATCH * CPB)          /* 1024 chunks total */
#define NSEG 16
#define SEGLEN (CPB / NSEG)         /* 16 */
#define LN_EPS_F 1e-5f
#define FULLMASK 0xffffffffu
#define SENT_BITS 0x7fbfffffu       /* NaN sentinel for unpublished stats */

// Scratch
__device__ float  g_S[NCHT * DIMN];          // chunk-final local z states (4 MB)
__device__ float  g_P[NCHT * DIMN];          // chunk entry carries (4 MB)
__device__ float  g_A[BATCH * NSEG * DIMN];  // segment aggregates (256 KB)
__device__ float2 g_stats[BATCH * SEQ];      // per-row (inv, nm) (256 KB)

__device__ __forceinline__ float sigm_om(const float* __restrict__ alphas, int head) {
    float al = __ldg(alphas + head);
    return 1.0f - 1.0f / (1.0f + expf(-al));      // om = 1 - sigmoid(alpha)
}
__device__ __forceinline__ float pow32(float om) {
    float t = om * om;  t = t * t;  t = t * t;  t = t * t;  t = t * t;   // om^32
    return t;
}

// ---------------- Pass 1: warp-specialized LN stats + local z-scan ----------
// 512 threads: warps 0-7 = scan (thread owns channels tid*4..+3, one head,
// no shuffles/barriers), warps 8-15 = stats (row r handled by warp 8 + r%8;
// re-reads the row from global -- L1/miss-in-flight hit -- reduces privately,
// publishes (inv,nm) as one volatile 8B smem store). 8 stats warps halve the
// per-row stats production latency (the critical path at 4 warps).
__global__ __launch_bounds__(512, 2) void mhesa_pass1(
    const float* __restrict__ x, const float* __restrict__ gamma,
    const float* __restrict__ beta, const float* __restrict__ alphas)
{
    __shared__ float2 s_st[RCH];

    const int tid = threadIdx.x;
    const int chunk = blockIdx.x;               // 0..NCHT-1
    const int bat = chunk >> 8;                 // / CPB
    const int c = chunk & (CPB - 1);
    const size_t rowbase = ((size_t)bat * SEQ + (size_t)c * RCH) * DIMN;
    const int row0 = bat * SEQ + c * RCH;

    if (tid < RCH) s_st[tid] = make_float2(__uint_as_float(SENT_BITS), 0.f);
    __syncthreads();

    if (tid < 256) {
        // ================= scan role =================
        const int ch4 = tid * 4;
        const float om = sigm_om(alphas, ch4 >> 7);
        const float4 g  = *(const float4*)(gamma + ch4);
        const float4 bb = *(const float4*)(beta + ch4);
        const float* xp = x + rowbase + ch4;

        float4 buf[4];
#pragma unroll
        for (int k = 0; k < 4; k++)
            buf[k] = __ldg((const float4*)(xp + (size_t)k * DIMN));

        float4 z = make_float4(0.f, 0.f, 0.f, 0.f);

        for (int rb = 0; rb < RCH; rb += 4) {
#pragma unroll
            for (int k = 0; k < 4; k++) {
                const int r = rb + k;
                const float4 v = buf[k];
                if (r + 4 < RCH)
                    buf[k] = __ldg((const float4*)(xp + (size_t)(r + 4) * DIMN));
                // wait for stats of row r (usually already published)
                float inv, nm;
                {
                    const unsigned addr =
                        (unsigned)__cvta_generic_to_shared(&s_st[r]);
                    asm volatile("ld.volatile.shared.v2.f32 {%0,%1}, [%2];"
                                 : "=f"(inv), "=f"(nm) : "r"(addr));
                    while (__float_as_uint(inv) == SENT_BITS) {
                        __nanosleep(32);
                        asm volatile("ld.volatile.shared.v2.f32 {%0,%1}, [%2];"
                                     : "=f"(inv), "=f"(nm) : "r"(addr));
                    }
                }
                float4 u;
                u.x = fmaf(fmaf(v.x, inv, nm), g.x, bb.x);
                u.y = fmaf(fmaf(v.y, inv, nm), g.y, bb.y);
                u.z = fmaf(fmaf(v.z, inv, nm), g.z, bb.z);
                u.w = fmaf(fmaf(v.w, inv, nm), g.w, bb.w);
                z.x = fmaf(om, z.x, u.x);
                z.y = fmaf(om, z.y, u.y);
                z.z = fmaf(om, z.z, u.z);
                z.w = fmaf(om, z.w, u.w);
            }
        }
        *(float4*)(g_S + (size_t)chunk * DIMN + tid * 4) = z;
    } else {
        // ================= stats role =================
        const int sw = (tid >> 5) - 8;          // 0..7
        const int lane = tid & 31;
        for (int r = sw; r < RCH; r += 8) {
            const float* xp = x + rowbase + (size_t)r * DIMN + lane * 4;
            float4 v[8];
#pragma unroll
            for (int j = 0; j < 8; j++)
                v[j] = __ldg((const float4*)(xp + j * 128));
            float sum = 0.f, sq = 0.f;
#pragma unroll
            for (int j = 0; j < 8; j++) {
                sum += (v[j].x + v[j].y) + (v[j].z + v[j].w);
                sq = fmaf(v[j].x, v[j].x, sq);
                sq = fmaf(v[j].y, v[j].y, sq);
                sq = fmaf(v[j].z, v[j].z, sq);
                sq = fmaf(v[j].w, v[j].w, sq);
            }
#pragma unroll
            for (int off = 16; off; off >>= 1) {
                sum += __shfl_xor_sync(FULLMASK, sum, off);
                sq  += __shfl_xor_sync(FULLMASK, sq,  off);
            }
            if (lane == 0) {
                const float mean = sum * (1.0f / (float)DIMN);
                const float var  = fmaf(sq, 1.0f / (float)DIMN, -mean * mean);
                const float inv  = rsqrtf(var + LN_EPS_F);
                const float nm   = -mean * inv;
                g_stats[row0 + r] = make_float2(inv, nm);
                const unsigned addr =
                    (unsigned)__cvta_generic_to_shared(&s_st[r]);
                asm volatile("st.volatile.shared.v2.f32 [%0], {%1,%2};"
                             :: "r"(addr), "f"(inv), "f"(nm));
            }
        }
    }
}

// ---------------- Carry phase A: segment aggregates ----------------
// A[b,seg] = sum_j omC^(SEGLEN-1-j) * S[b, seg*SEGLEN + j]
__global__ void mhesa_carryA(const float* __restrict__ alphas)
{
    const int t = blockIdx.x * 256 + threadIdx.x;       // 0..65535
    const int ch = t & (DIMN - 1);
    const int rest = t >> 10;                            // b*NSEG + seg
    const float omC = pow32(sigm_om(alphas, ch >> 7));
    const size_t base = (size_t)rest * SEGLEN * DIMN + ch;
    float s[SEGLEN];
#pragma unroll
    for (int j = 0; j < SEGLEN; j++) s[j] = g_S[base + (size_t)j * DIMN];
    float A = 0.f;
#pragma unroll
    for (int j = 0; j < SEGLEN; j++) A = fmaf(omC, A, s[j]);
    g_A[(size_t)rest * DIMN + ch] = A;
}

// ---------------- Carry phase C: chunk entry carries ----------------
__global__ void mhesa_carryC(const float* __restrict__ alphas)
{
    const int t = blockIdx.x * 256 + threadIdx.x;
    const int ch = t & (DIMN - 1);
    const int rest = t >> 10;
    const int seg = rest & (NSEG - 1);
    const int b = rest >> 4;
    const float omC = pow32(sigm_om(alphas, ch >> 7));
    float omSeg = omC;                                   // omC^SEGLEN = om^512
    omSeg = omSeg * omSeg; omSeg = omSeg * omSeg;
    omSeg = omSeg * omSeg; omSeg = omSeg * omSeg;

    float p = 0.f;
    const size_t abase = (size_t)b * NSEG * DIMN + ch;
    for (int s2 = 0; s2 < seg; s2++)
        p = fmaf(omSeg, p, g_A[abase + (size_t)s2 * DIMN]);

    const size_t base = (size_t)rest * SEGLEN * DIMN + ch;
    float s[SEGLEN];
#pragma unroll
    for (int j = 0; j < SEGLEN; j++) s[j] = g_S[base + (size_t)j * DIMN];
#pragma unroll
    for (int j = 0; j < SEGLEN; j++) {
        g_P[base + (size_t)j * DIMN] = p;
        p = fmaf(omC, p, s[j]);
    }
}

// ---------------- Pass 2: pure stream, no reductions ----------------
__global__ __launch_bounds__(256, 4) void mhesa_pass2(
    const float* __restrict__ x, const float* __restrict__ gamma,
    const float* __restrict__ beta, const float* __restrict__ alphas,
    const float* __restrict__ paramD, float* __restrict__ out)
{
    const int tid = threadIdx.x;
    const int ch4 = tid * 4;
    const int chunk = NCHT - 1 - blockIdx.x;    // reverse: reuse pass1's L2 tail
    const int bat = chunk >> 8;
    const int c = chunk & (CPB - 1);

    const float om = sigm_om(alphas, ch4 >> 7);
    const float a = 1.0f - om;
    const float4 g  = *(const float4*)(gamma + ch4);
    const float4 bb = *(const float4*)(beta + ch4);
    const float4 d  = *(const float4*)(paramD + ch4);

    const size_t base = ((size_t)bat * SEQ + (size_t)c * RCH) * DIMN + ch4;
    const int row0 = bat * SEQ + c * RCH;

    float4 z = *(const float4*)(g_P + (size_t)chunk * DIMN + ch4);

    float4 buf[4];
#pragma unroll
    for (int k = 0; k < 4; k++)
        buf[k] = __ldg((const float4*)(x + base + (size_t)k * DIMN));

    for (int rb = 0; rb < RCH; rb += 4) {
#pragma unroll
        for (int k = 0; k < 4; k++) {
            const int r = rb + k;
            const float4 v = buf[k];
            if (r + 4 < RCH)
                buf[k] = __ldg((const float4*)(x + base + (size_t)(r + 4) * DIMN));
            const float2 st = __ldg(&g_stats[row0 + r]);   // (inv, nm), warp-broadcast
            const float inv = st.x, nm = st.y;
            float4 u;
            u.x = fmaf(fmaf(v.x, inv, nm), g.x, bb.x);
            u.y = fmaf(fmaf(v.y, inv, nm), g.y, bb.y);
            u.z = fmaf(fmaf(v.z, inv, nm), g.z, bb.z);
            u.w = fmaf(fmaf(v.w, inv, nm), g.w, bb.w);
            z.x = fmaf(om, z.x, u.x);
            z.y = fmaf(om, z.y, u.y);
            z.z = fmaf(om, z.z, u.z);
            z.w = fmaf(om, z.w, u.w);
            float4 o;
            o.x = fmaf(u.x, d.x, a * z.x);
            o.y = fmaf(u.y, d.y, a * z.y);
            o.z = fmaf(u.z, d.z, a * z.z);
            o.w = fmaf(u.w, d.w, a * z.w);
            __stcs((float4*)(out + base + (size_t)r * DIMN), o);
        }
    }
}

extern "C" void kernel_launch(void* const* d_in, const int* in_sizes, int n_in,
                              void* d_out, int out_size)
{
    const float* x      = (const float*)d_in[0];
    const float* gamma  = (const float*)d_in[1];
    const float* beta   = (const float*)d_in[2];
    const float* alphas = (const float*)d_in[3];
    const float* paramD = (const float*)d_in[4];
    float* out = (float*)d_out;

    mhesa_pass1<<<NCHT, 512>>>(x, gamma, beta, alphas);
    mhesa_carryA<<<(BATCH * NSEG * DIMN) / 256, 256>>>(alphas);
    mhesa_carryC<<<(BATCH * NSEG * DIMN) / 256, 256>>>(alphas);
    mhesa_pass2<<<NCHT, 256>>>(x, gamma, beta, alphas, paramD, out);
}